// round 2
// baseline (speedup 1.0000x reference)
#include <cuda_runtime.h>

// ---------------------------------------------------------------------------
// GCN, 4 layers + heads. R2:
//  - layers 0-2: agg (gather CSR) -> GEMM with packed fma.rn.f32x2
//  - layer 3 + PI/V heads collapsed algebraically (layer 3 is linear):
//      z[u]  = hs2[u] . (W3@Wp),  z2[u] = hs2[u] . (W3@Wv)
//      PI[v] = ndst[v]*sum_{u in N(v)} z[u] + (b3.Wp + bp)
//      V     = sum_v ndst[v]*sum z2[u] + 50000*(b3.Wv) + bv
// ---------------------------------------------------------------------------

constexpr int NN = 50000;
constexpr int NE = 800000;
constexpr int F  = 128;

__device__ int    g_outdeg[NN];
__device__ int    g_indeg[NN];
__device__ float  g_nsrc[NN];
__device__ float  g_ndst[NN];
__device__ int    g_rowptr[NN + 1];
__device__ int    g_cursor[NN];
__device__ int    g_esrc[NE];
__device__ float  g_hs[(size_t)NN * F];    // scaled features (gather source)
__device__ float  g_agg[(size_t)NN * F];   // aggregated * norm_dst (GEMM input)
__device__ float2 g_zz[NN];                // (z, z2) per node
__device__ float  g_q[F];                  // W3 @ Wp
__device__ float  g_q2[F];                 // W3 @ Wv
__device__ float  g_cPI;

typedef unsigned long long ull;

__device__ __forceinline__ void fma2(ull& d, ull a, ull b) {
    asm("fma.rn.f32x2 %0, %1, %2, %0;" : "+l"(d) : "l"(a), "l"(b));
}
__device__ __forceinline__ ull pack2(float lo, float hi) {
    ull r; asm("mov.b64 %0, {%1, %2};" : "=l"(r) : "f"(lo), "f"(hi)); return r;
}
__device__ __forceinline__ void unpack2(float& lo, float& hi, ull v) {
    asm("mov.b64 {%0, %1}, %2;" : "=f"(lo), "=f"(hi) : "l"(v));
}

// --------------------------- setup ----------------------------------------

__global__ void k_zero() {
    int i = blockIdx.x * blockDim.x + threadIdx.x;
    if (i < NN) { g_outdeg[i] = 0; g_indeg[i] = 0; }
}

__global__ void k_hist(const int* __restrict__ src, const int* __restrict__ dst) {
    int e = blockIdx.x * blockDim.x + threadIdx.x;
    if (e < NE) {
        atomicAdd(&g_outdeg[src[e]], 1);
        atomicAdd(&g_indeg[dst[e]], 1);
    }
}

// Single-block scan: per-thread chunk of 49 + one 1024-wide block scan.
__global__ void k_scan() {
    constexpr int CH = (NN + 1023) / 1024;   // 49
    __shared__ int ts[1024];
    int t = threadIdx.x;
    int base = t * CH;
    // pass 1: local prefix written in place to rowptr, thread total
    int s = 0;
    for (int i = 0; i < CH; i++) {
        int idx = base + i;
        int v = (idx < NN) ? g_indeg[idx] : 0;
        if (idx < NN) g_rowptr[idx] = s;   // local exclusive prefix
        s += v;
    }
    ts[t] = s;
    __syncthreads();
    // inclusive Hillis-Steele over 1024 thread totals
    for (int off = 1; off < 1024; off <<= 1) {
        int v = (t >= off) ? ts[t - off] : 0;
        __syncthreads();
        ts[t] += v;
        __syncthreads();
    }
    int offset = ts[t] - s;  // exclusive prefix of thread totals
    for (int i = 0; i < CH; i++) {
        int idx = base + i;
        if (idx < NN) {
            int p = g_rowptr[idx] + offset;
            g_rowptr[idx] = p;
            g_cursor[idx] = p;
        }
    }
    if (t == 1023) g_rowptr[NN] = ts[1023];
}

__global__ void k_norm() {
    int i = blockIdx.x * blockDim.x + threadIdx.x;
    if (i < NN) {
        g_nsrc[i] = rsqrtf((float)max(g_outdeg[i], 1));
        g_ndst[i] = rsqrtf((float)max(g_indeg[i], 1));
    }
}

__global__ void k_fill(const int* __restrict__ src, const int* __restrict__ dst) {
    int e = blockIdx.x * blockDim.x + threadIdx.x;
    if (e < NE) {
        int p = atomicAdd(&g_cursor[dst[e]], 1);
        g_esrc[p] = src[e];
    }
}

__global__ void k_scale0(const float* __restrict__ feats) {
    int i = blockIdx.x * blockDim.x + threadIdx.x;   // float4 index
    constexpr int TOT = NN * F / 4;
    if (i < TOT) {
        int node = i >> 5;
        float s = g_nsrc[node];
        float4 x = ((const float4*)feats)[i];
        x.x *= s; x.y *= s; x.z *= s; x.w *= s;
        ((float4*)g_hs)[i] = x;
    }
}

// q = W3 @ Wp, q2 = W3 @ Wv, consts; also init out[NN] = cV.
__global__ void k_prep(const float* __restrict__ W3, const float* __restrict__ b3,
                       const float* __restrict__ Wp, const float* __restrict__ bp,
                       const float* __restrict__ Wv, const float* __restrict__ bv,
                       float* __restrict__ out) {
    int k = threadIdx.x;   // 128 threads
    float a = 0.f, c = 0.f;
    for (int j = 0; j < 64; j++) {
        float w = W3[k * 64 + j];
        a += w * Wp[j];
        c += w * Wv[j];
    }
    g_q[k] = a;
    g_q2[k] = c;
    if (k == 0) {
        float cp = 0.f, cv = 0.f;
        for (int j = 0; j < 64; j++) { cp += b3[j] * Wp[j]; cv += b3[j] * Wv[j]; }
        g_cPI = cp + bp[0];
        out[NN] = (float)NN * cv + bv[0];
    }
}

// --------------------------- aggregation ----------------------------------
// One warp per node; lane owns one float4. 4-deep unroll for MLP.

__global__ void k_agg() {
    int v = blockIdx.x * (blockDim.x >> 5) + (threadIdx.x >> 5);
    if (v >= NN) return;
    int lane = threadIdx.x & 31;
    int beg = g_rowptr[v], end = g_rowptr[v + 1];
    const float4* hs4 = (const float4*)g_hs;
    float4 a0 = make_float4(0.f, 0.f, 0.f, 0.f);
    float4 a1 = a0, a2 = a0, a3 = a0;
    int e = beg;
    for (; e + 3 < end; e += 4) {
        int u0 = g_esrc[e],     u1 = g_esrc[e + 1];
        int u2 = g_esrc[e + 2], u3 = g_esrc[e + 3];
        float4 x0 = hs4[u0 * 32 + lane];
        float4 x1 = hs4[u1 * 32 + lane];
        float4 x2 = hs4[u2 * 32 + lane];
        float4 x3 = hs4[u3 * 32 + lane];
        a0.x += x0.x; a0.y += x0.y; a0.z += x0.z; a0.w += x0.w;
        a1.x += x1.x; a1.y += x1.y; a1.z += x1.z; a1.w += x1.w;
        a2.x += x2.x; a2.y += x2.y; a2.z += x2.z; a2.w += x2.w;
        a3.x += x3.x; a3.y += x3.y; a3.z += x3.z; a3.w += x3.w;
    }
    for (; e < end; e++) {
        int u = g_esrc[e];
        float4 x = hs4[u * 32 + lane];
        a0.x += x.x; a0.y += x.y; a0.z += x.z; a0.w += x.w;
    }
    float nd = g_ndst[v];
    float4 o;
    o.x = ((a0.x + a1.x) + (a2.x + a3.x)) * nd;
    o.y = ((a0.y + a1.y) + (a2.y + a3.y)) * nd;
    o.z = ((a0.z + a1.z) + (a2.z + a3.z)) * nd;
    o.w = ((a0.w + a1.w) + (a2.w + a3.w)) * nd;
    ((float4*)g_agg)[v * 32 + lane] = o;
}

// ------------------------------ GEMM ---------------------------------------
// g_hs = relu(g_agg @ W + b) * nsrc.  128x128 weights, packed f32x2 FMAs.
// Block 256 thr: 64 rows x 128 cols. Thread: 4 rows (strided 16) x 8 cols.
// A in smem pad-129 (conflict-free strided-row LDS); W via warp-uniform ldg.64.

__global__ void __launch_bounds__(256) k_gemm(const float* __restrict__ W,
                                              const float* __restrict__ b) {
    constexpr int K = 128, PAD = 129;
    __shared__ float sA[64 * PAD];

    int tid = threadIdx.x;
    int row0 = blockIdx.x * 64;
    const float4* A4 = (const float4*)g_agg;

    #pragma unroll
    for (int i = tid; i < 64 * 32; i += 256) {
        int r = i >> 5, c4 = i & 31;
        int gr = row0 + r;
        float4 v = (gr < NN) ? A4[gr * 32 + c4] : make_float4(0.f, 0.f, 0.f, 0.f);
        float* p = &sA[r * PAD + c4 * 4];
        p[0] = v.x; p[1] = v.y; p[2] = v.z; p[3] = v.w;
    }
    __syncthreads();

    int cg = tid >> 4;        // 0..15, uniform per half-warp -> W loads broadcast
    int rg = tid & 15;        // 0..15, lane-varying -> sA conflict-free (pad 129)
    int c0 = cg * 8;

    ull acc[4][4];
    #pragma unroll
    for (int r = 0; r < 4; r++)
        #pragma unroll
        for (int j = 0; j < 4; j++) acc[r][j] = 0ull;

    const ull* Wq = (const ull*)W;
    #pragma unroll 4
    for (int k = 0; k < K; k++) {
        ull w0 = __ldg(&Wq[(k * 128 + c0) >> 1]);
        ull w1 = __ldg(&Wq[(k * 128 + c0 + 2) >> 1]);
        ull w2 = __ldg(&Wq[(k * 128 + c0 + 4) >> 1]);
        ull w3 = __ldg(&Wq[(k * 128 + c0 + 6) >> 1]);
        #pragma unroll
        for (int r = 0; r < 4; r++) {
            float a = sA[(rg + 16 * r) * PAD + k];
            ull aa = pack2(a, a);
            fma2(acc[r][0], aa, w0);
            fma2(acc[r][1], aa, w1);
            fma2(acc[r][2], aa, w2);
            fma2(acc[r][3], aa, w3);
        }
    }

    float4 bb0, bb1;
    bb0 = __ldg((const float4*)&b[c0]);
    bb1 = __ldg((const float4*)&b[c0 + 4]);
    float bias[8] = {bb0.x, bb0.y, bb0.z, bb0.w, bb1.x, bb1.y, bb1.z, bb1.w};

    #pragma unroll
    for (int r = 0; r < 4; r++) {
        int gr = row0 + rg + 16 * r;
        if (gr < NN) {
            float sc = g_nsrc[gr];
            float o[8];
            #pragma unroll
            for (int j = 0; j < 4; j++) unpack2(o[2 * j], o[2 * j + 1], acc[r][j]);
            #pragma unroll
            for (int j = 0; j < 8; j++)
                o[j] = fmaxf(o[j] + bias[j], 0.f) * sc;
            float4* dst = (float4*)&g_hs[(size_t)gr * 128 + c0];
            dst[0] = make_float4(o[0], o[1], o[2], o[3]);
            dst[1] = make_float4(o[4], o[5], o[6], o[7]);
        }
    }
}

// ---------------------- collapsed layer 3 + heads --------------------------

// z[u] = hs.q, z2[u] = hs.q2  (warp per node)
__global__ void k_z() {
    int v = blockIdx.x * (blockDim.x >> 5) + (threadIdx.x >> 5);
    if (v >= NN) return;
    int lane = threadIdx.x & 31;
    float4 h = ((const float4*)g_hs)[v * 32 + lane];
    float4 q = ((const float4*)g_q)[lane];
    float4 q2 = ((const float4*)g_q2)[lane];
    float z  = h.x * q.x  + h.y * q.y  + h.z * q.z  + h.w * q.w;
    float z2 = h.x * q2.x + h.y * q2.y + h.z * q2.z + h.w * q2.w;
    #pragma unroll
    for (int off = 16; off; off >>= 1) {
        z  += __shfl_xor_sync(0xffffffff, z,  off);
        z2 += __shfl_xor_sync(0xffffffff, z2, off);
    }
    if (lane == 0) g_zz[v] = make_float2(z, z2);
}

// PI[v] = ndst*sum z + cPI ; V += ndst*sum z2 (block-reduced atomic)
__global__ void k_zagg(float* __restrict__ out) {
    __shared__ float red[256];
    int v = blockIdx.x * blockDim.x + threadIdx.x;
    float vp = 0.f;
    if (v < NN) {
        int beg = g_rowptr[v], end = g_rowptr[v + 1];
        float s0 = 0.f, s1 = 0.f, t0 = 0.f, t1 = 0.f;
        int e = beg;
        for (; e + 1 < end; e += 2) {
            float2 a = g_zz[g_esrc[e]];
            float2 b = g_zz[g_esrc[e + 1]];
            s0 += a.x; t0 += a.y;
            s1 += b.x; t1 += b.y;
        }
        if (e < end) {
            float2 a = g_zz[g_esrc[e]];
            s0 += a.x; t0 += a.y;
        }
        float nd = g_ndst[v];
        out[v] = nd * (s0 + s1) + g_cPI;
        vp = nd * (t0 + t1);
    }
    red[threadIdx.x] = vp;
    __syncthreads();
    for (int off = 128; off; off >>= 1) {
        if (threadIdx.x < off) red[threadIdx.x] += red[threadIdx.x + off];
        __syncthreads();
    }
    if (threadIdx.x == 0) atomicAdd(&out[NN], red[0]);
}

// --------------------------- launch ----------------------------------------

extern "C" void kernel_launch(void* const* d_in, const int* in_sizes, int n_in,
                              void* d_out, int out_size) {
    const float* feats = (const float*)d_in[0];
    const int*   src   = (const int*)d_in[1];
    const int*   dst   = (const int*)d_in[2];
    const float* W0 = (const float*)d_in[3];  const float* b0 = (const float*)d_in[4];
    const float* W1 = (const float*)d_in[5];  const float* b1 = (const float*)d_in[6];
    const float* W2 = (const float*)d_in[7];  const float* b2 = (const float*)d_in[8];
    const float* W3 = (const float*)d_in[9];  const float* b3 = (const float*)d_in[10];
    const float* Wp = (const float*)d_in[11]; const float* bp = (const float*)d_in[12];
    const float* Wv = (const float*)d_in[13]; const float* bv = (const float*)d_in[14];
    float* out = (float*)d_out;

    k_zero<<<(NN + 255) / 256, 256>>>();
    k_hist<<<(NE + 255) / 256, 256>>>(src, dst);
    k_scan<<<1, 1024>>>();
    k_norm<<<(NN + 255) / 256, 256>>>();
    k_fill<<<(NE + 255) / 256, 256>>>(src, dst);
    k_prep<<<1, 128>>>(W3, b3, Wp, bp, Wv, bv, out);
    k_scale0<<<(NN * F / 4 + 255) / 256, 256>>>(feats);

    const int aggGrid  = (NN + 7) / 8;       // 8 warps/block
    const int gemmGrid = (NN + 63) / 64;

    k_agg<<<aggGrid, 256>>>();
    k_gemm<<<gemmGrid, 256>>>(W0, b0);
    k_agg<<<aggGrid, 256>>>();
    k_gemm<<<gemmGrid, 256>>>(W1, b1);
    k_agg<<<aggGrid, 256>>>();
    k_gemm<<<gemmGrid, 256>>>(W2, b2);

    k_z<<<aggGrid, 256>>>();
    k_zagg<<<(NN + 255) / 256, 256>>>(out);
}

// round 3
// speedup vs baseline: 1.1900x; 1.1900x over previous
#include <cuda_runtime.h>

// ---------------------------------------------------------------------------
// GCN, 4 layers + heads. R3:
//  - layers 0-2: agg (gather CSR) -> smem-staged register-tiled GEMM (fma.rn.f32x2)
//  - layer 3 + PI/V heads collapsed algebraically (layer 3 is linear)
// ---------------------------------------------------------------------------

constexpr int NN = 50000;
constexpr int NE = 800000;
constexpr int F  = 128;

__device__ int    g_outdeg[NN];
__device__ int    g_indeg[NN];
__device__ float  g_nsrc[NN];
__device__ float  g_ndst[NN];
__device__ int    g_rowptr[NN + 1];
__device__ int    g_cursor[NN];
__device__ int    g_esrc[NE];
__device__ float  g_hs[(size_t)NN * F];    // scaled features (gather source)
__device__ float  g_agg[(size_t)NN * F];   // aggregated * norm_dst (GEMM input)
__device__ float2 g_zz[NN];                // (z, z2) per node
__device__ float  g_q[F];                  // W3 @ Wp
__device__ float  g_q2[F];                 // W3 @ Wv
__device__ float  g_cPI;

typedef unsigned long long ull;

__device__ __forceinline__ void fma2(ull& d, ull a, ull b) {
    asm("fma.rn.f32x2 %0, %1, %2, %0;" : "+l"(d) : "l"(a), "l"(b));
}
__device__ __forceinline__ ull pack2(float lo, float hi) {
    ull r; asm("mov.b64 %0, {%1, %2};" : "=l"(r) : "f"(lo), "f"(hi)); return r;
}
__device__ __forceinline__ void unpack2(float& lo, float& hi, ull v) {
    asm("mov.b64 {%0, %1}, %2;" : "=f"(lo), "=f"(hi) : "l"(v));
}

// --------------------------- setup ----------------------------------------

__global__ void k_zero() {
    int i = blockIdx.x * blockDim.x + threadIdx.x;
    if (i < NN) { g_outdeg[i] = 0; g_indeg[i] = 0; }
}

__global__ void k_hist(const int* __restrict__ src, const int* __restrict__ dst) {
    int e = blockIdx.x * blockDim.x + threadIdx.x;
    if (e < NE) {
        atomicAdd(&g_outdeg[src[e]], 1);
        atomicAdd(&g_indeg[dst[e]], 1);
    }
}

// Single-block scan: per-thread chunk of 49 + one 1024-wide block scan.
__global__ void k_scan() {
    constexpr int CH = (NN + 1023) / 1024;   // 49
    __shared__ int ts[1024];
    int t = threadIdx.x;
    int base = t * CH;
    int s = 0;
    for (int i = 0; i < CH; i++) {
        int idx = base + i;
        int v = (idx < NN) ? g_indeg[idx] : 0;
        if (idx < NN) g_rowptr[idx] = s;
        s += v;
    }
    ts[t] = s;
    __syncthreads();
    for (int off = 1; off < 1024; off <<= 1) {
        int v = (t >= off) ? ts[t - off] : 0;
        __syncthreads();
        ts[t] += v;
        __syncthreads();
    }
    int offset = ts[t] - s;
    for (int i = 0; i < CH; i++) {
        int idx = base + i;
        if (idx < NN) {
            int p = g_rowptr[idx] + offset;
            g_rowptr[idx] = p;
            g_cursor[idx] = p;
        }
    }
    if (t == 1023) g_rowptr[NN] = ts[1023];
}

__global__ void k_norm() {
    int i = blockIdx.x * blockDim.x + threadIdx.x;
    if (i < NN) {
        g_nsrc[i] = rsqrtf((float)max(g_outdeg[i], 1));
        g_ndst[i] = rsqrtf((float)max(g_indeg[i], 1));
    }
}

__global__ void k_fill(const int* __restrict__ src, const int* __restrict__ dst) {
    int e = blockIdx.x * blockDim.x + threadIdx.x;
    if (e < NE) {
        int p = atomicAdd(&g_cursor[dst[e]], 1);
        g_esrc[p] = src[e];
    }
}

__global__ void k_scale0(const float* __restrict__ feats) {
    int i = blockIdx.x * blockDim.x + threadIdx.x;
    constexpr int TOT = NN * F / 4;
    if (i < TOT) {
        int node = i >> 5;
        float s = g_nsrc[node];
        float4 x = ((const float4*)feats)[i];
        x.x *= s; x.y *= s; x.z *= s; x.w *= s;
        ((float4*)g_hs)[i] = x;
    }
}

__global__ void k_prep(const float* __restrict__ W3, const float* __restrict__ b3,
                       const float* __restrict__ Wp, const float* __restrict__ bp,
                       const float* __restrict__ Wv, const float* __restrict__ bv,
                       float* __restrict__ out) {
    int k = threadIdx.x;   // 128 threads
    float a = 0.f, c = 0.f;
    for (int j = 0; j < 64; j++) {
        float w = W3[k * 64 + j];
        a += w * Wp[j];
        c += w * Wv[j];
    }
    g_q[k] = a;
    g_q2[k] = c;
    if (k == 0) {
        float cp = 0.f, cv = 0.f;
        for (int j = 0; j < 64; j++) { cp += b3[j] * Wp[j]; cv += b3[j] * Wv[j]; }
        g_cPI = cp + bp[0];
        out[NN] = (float)NN * cv + bv[0];
    }
}

// --------------------------- aggregation ----------------------------------

__global__ void k_agg() {
    int v = blockIdx.x * (blockDim.x >> 5) + (threadIdx.x >> 5);
    if (v >= NN) return;
    int lane = threadIdx.x & 31;
    int beg = g_rowptr[v], end = g_rowptr[v + 1];
    const float4* hs4 = (const float4*)g_hs;
    float4 a0 = make_float4(0.f, 0.f, 0.f, 0.f);
    float4 a1 = a0, a2 = a0, a3 = a0;
    int e = beg;
    for (; e + 3 < end; e += 4) {
        int u0 = g_esrc[e],     u1 = g_esrc[e + 1];
        int u2 = g_esrc[e + 2], u3 = g_esrc[e + 3];
        float4 x0 = hs4[u0 * 32 + lane];
        float4 x1 = hs4[u1 * 32 + lane];
        float4 x2 = hs4[u2 * 32 + lane];
        float4 x3 = hs4[u3 * 32 + lane];
        a0.x += x0.x; a0.y += x0.y; a0.z += x0.z; a0.w += x0.w;
        a1.x += x1.x; a1.y += x1.y; a1.z += x1.z; a1.w += x1.w;
        a2.x += x2.x; a2.y += x2.y; a2.z += x2.z; a2.w += x2.w;
        a3.x += x3.x; a3.y += x3.y; a3.z += x3.z; a3.w += x3.w;
    }
    for (; e < end; e++) {
        int u = g_esrc[e];
        float4 x = hs4[u * 32 + lane];
        a0.x += x.x; a0.y += x.y; a0.z += x.z; a0.w += x.w;
    }
    float nd = g_ndst[v];
    float4 o;
    o.x = ((a0.x + a1.x) + (a2.x + a3.x)) * nd;
    o.y = ((a0.y + a1.y) + (a2.y + a3.y)) * nd;
    o.z = ((a0.z + a1.z) + (a2.z + a3.z)) * nd;
    o.w = ((a0.w + a1.w) + (a2.w + a3.w)) * nd;
    ((float4*)g_agg)[v * 32 + lane] = o;
}

// ------------------------------ GEMM ---------------------------------------
// g_hs = relu(g_agg @ W + b) * nsrc, W is 128x128 row-major.
// Block: 128 rows x 64 cols, 256 threads. Thread: 8 rows x 4 cols.
// Both operands staged in dynamic smem; A transposed ([k][row], stride 132 ->
// conflict-free transpose-store AND 16B-aligned row-pair reads).
// Inner loop: 2x LDS.128 (A row-pairs as ull), 1x LDS.128 (W), 4 pack, 16 FMA2.

constexpr int SATS = 132;                      // sAT row stride (floats)
constexpr int GEMM_SMEM = (128 * SATS + 128 * 64) * 4;   // 100352 B

__global__ void __launch_bounds__(256) k_gemm(const float* __restrict__ W,
                                              const float* __restrict__ b) {
    extern __shared__ float sm[];
    float* sAT = sm;                 // [k][row], stride SATS
    float* sW  = sm + 128 * SATS;    // [k][c],   stride 64

    int tid  = threadIdx.x;
    int lane = tid & 31;
    int warp = tid >> 5;
    int row0 = (blockIdx.x >> 1) * 128;
    int col0 = (blockIdx.x & 1) * 64;

    // --- stage A transposed: lanes map to rows (conflict-free STS) ---
    const float4* A4 = (const float4*)g_agg;
    #pragma unroll
    for (int it = 0; it < 16; it++) {
        int idx = it * 8 + warp;          // 0..127
        int rg  = idx & 3;                // row group of 32
        int c4  = idx >> 2;               // k-chunk 0..31
        int r   = rg * 32 + lane;
        int gr  = row0 + r;
        float4 v = (gr < NN) ? A4[gr * 32 + c4] : make_float4(0.f, 0.f, 0.f, 0.f);
        sAT[(4 * c4 + 0) * SATS + r] = v.x;
        sAT[(4 * c4 + 1) * SATS + r] = v.y;
        sAT[(4 * c4 + 2) * SATS + r] = v.z;
        sAT[(4 * c4 + 3) * SATS + r] = v.w;
    }
    // --- stage W tile (coalesced load + store) ---
    const float4* W4 = (const float4*)W;
    float4* sW4 = (float4*)sW;
    #pragma unroll
    for (int it = 0; it < 8; it++) {
        int i  = it * 256 + tid;          // 0..2047
        int k  = i >> 4;
        int cq = i & 15;
        sW4[k * 16 + cq] = W4[k * 32 + (col0 >> 2) + cq];
    }
    __syncthreads();

    int tx = tid & 15;                    // col group: cols col0 + tx*4
    int ty = tid >> 4;                    // row group: rows row0 + ty*8

    ull acc[4][4];                        // [row-pair][col]
    #pragma unroll
    for (int rp = 0; rp < 4; rp++)
        #pragma unroll
        for (int c = 0; c < 4; c++) acc[rp][c] = 0ull;

    const float* aBase = &sAT[ty * 8];
    const float* wBase = &sW[tx * 4];

    #pragma unroll 8
    for (int k = 0; k < 128; k++) {
        const ull* aq = (const ull*)(aBase + k * SATS);
        ull ra0 = aq[0], ra1 = aq[1], ra2 = aq[2], ra3 = aq[3];
        float4 w = *(const float4*)(wBase + k * 64);
        ull w0 = pack2(w.x, w.x);
        ull w1 = pack2(w.y, w.y);
        ull w2 = pack2(w.z, w.z);
        ull w3 = pack2(w.w, w.w);
        fma2(acc[0][0], ra0, w0); fma2(acc[0][1], ra0, w1);
        fma2(acc[0][2], ra0, w2); fma2(acc[0][3], ra0, w3);
        fma2(acc[1][0], ra1, w0); fma2(acc[1][1], ra1, w1);
        fma2(acc[1][2], ra1, w2); fma2(acc[1][3], ra1, w3);
        fma2(acc[2][0], ra2, w0); fma2(acc[2][1], ra2, w1);
        fma2(acc[2][2], ra2, w2); fma2(acc[2][3], ra2, w3);
        fma2(acc[3][0], ra3, w0); fma2(acc[3][1], ra3, w1);
        fma2(acc[3][2], ra3, w2); fma2(acc[3][3], ra3, w3);
    }

    float4 bb = __ldg((const float4*)&b[col0 + tx * 4]);
    #pragma unroll
    for (int rp = 0; rp < 4; rp++) {
        int re = row0 + ty * 8 + 2 * rp;      // even row of pair
        float oe[4], oo[4];
        #pragma unroll
        for (int c = 0; c < 4; c++) unpack2(oe[c], oo[c], acc[rp][c]);
        if (re < NN) {
            float sc = g_nsrc[re];
            float4 o;
            o.x = fmaxf(oe[0] + bb.x, 0.f) * sc;
            o.y = fmaxf(oe[1] + bb.y, 0.f) * sc;
            o.z = fmaxf(oe[2] + bb.z, 0.f) * sc;
            o.w = fmaxf(oe[3] + bb.w, 0.f) * sc;
            *(float4*)&g_hs[(size_t)re * 128 + col0 + tx * 4] = o;
        }
        if (re + 1 < NN) {
            float sc = g_nsrc[re + 1];
            float4 o;
            o.x = fmaxf(oo[0] + bb.x, 0.f) * sc;
            o.y = fmaxf(oo[1] + bb.y, 0.f) * sc;
            o.z = fmaxf(oo[2] + bb.z, 0.f) * sc;
            o.w = fmaxf(oo[3] + bb.w, 0.f) * sc;
            *(float4*)&g_hs[(size_t)(re + 1) * 128 + col0 + tx * 4] = o;
        }
    }
}

// ---------------------- collapsed layer 3 + heads --------------------------

__global__ void k_z() {
    int v = blockIdx.x * (blockDim.x >> 5) + (threadIdx.x >> 5);
    if (v >= NN) return;
    int lane = threadIdx.x & 31;
    float4 h = ((const float4*)g_hs)[v * 32 + lane];
    float4 q = ((const float4*)g_q)[lane];
    float4 q2 = ((const float4*)g_q2)[lane];
    float z  = h.x * q.x  + h.y * q.y  + h.z * q.z  + h.w * q.w;
    float z2 = h.x * q2.x + h.y * q2.y + h.z * q2.z + h.w * q2.w;
    #pragma unroll
    for (int off = 16; off; off >>= 1) {
        z  += __shfl_xor_sync(0xffffffff, z,  off);
        z2 += __shfl_xor_sync(0xffffffff, z2, off);
    }
    if (lane == 0) g_zz[v] = make_float2(z, z2);
}

__global__ void k_zagg(float* __restrict__ out) {
    __shared__ float red[256];
    int v = blockIdx.x * blockDim.x + threadIdx.x;
    float vp = 0.f;
    if (v < NN) {
        int beg = g_rowptr[v], end = g_rowptr[v + 1];
        float s0 = 0.f, s1 = 0.f, t0 = 0.f, t1 = 0.f;
        int e = beg;
        for (; e + 1 < end; e += 2) {
            float2 a = g_zz[g_esrc[e]];
            float2 b = g_zz[g_esrc[e + 1]];
            s0 += a.x; t0 += a.y;
            s1 += b.x; t1 += b.y;
        }
        if (e < end) {
            float2 a = g_zz[g_esrc[e]];
            s0 += a.x; t0 += a.y;
        }
        float nd = g_ndst[v];
        out[v] = nd * (s0 + s1) + g_cPI;
        vp = nd * (t0 + t1);
    }
    red[threadIdx.x] = vp;
    __syncthreads();
    for (int off = 128; off; off >>= 1) {
        if (threadIdx.x < off) red[threadIdx.x] += red[threadIdx.x + off];
        __syncthreads();
    }
    if (threadIdx.x == 0) atomicAdd(&out[NN], red[0]);
}

// --------------------------- launch ----------------------------------------

extern "C" void kernel_launch(void* const* d_in, const int* in_sizes, int n_in,
                              void* d_out, int out_size) {
    const float* feats = (const float*)d_in[0];
    const int*   src   = (const int*)d_in[1];
    const int*   dst   = (const int*)d_in[2];
    const float* W0 = (const float*)d_in[3];  const float* b0 = (const float*)d_in[4];
    const float* W1 = (const float*)d_in[5];  const float* b1 = (const float*)d_in[6];
    const float* W2 = (const float*)d_in[7];  const float* b2 = (const float*)d_in[8];
    const float* W3 = (const float*)d_in[9];  const float* b3 = (const float*)d_in[10];
    const float* Wp = (const float*)d_in[11]; const float* bp = (const float*)d_in[12];
    const float* Wv = (const float*)d_in[13]; const float* bv = (const float*)d_in[14];
    float* out = (float*)d_out;

    cudaFuncSetAttribute(k_gemm, cudaFuncAttributeMaxDynamicSharedMemorySize,
                         GEMM_SMEM);

    k_zero<<<(NN + 255) / 256, 256>>>();
    k_hist<<<(NE + 255) / 256, 256>>>(src, dst);
    k_scan<<<1, 1024>>>();
    k_norm<<<(NN + 255) / 256, 256>>>();
    k_fill<<<(NE + 255) / 256, 256>>>(src, dst);
    k_prep<<<1, 128>>>(W3, b3, Wp, bp, Wv, bv, out);
    k_scale0<<<(NN * F / 4 + 255) / 256, 256>>>(feats);

    const int aggGrid  = (NN + 7) / 8;           // 8 warps/block
    const int gemmGrid = ((NN + 127) / 128) * 2; // 2 col tiles

    k_agg<<<aggGrid, 256>>>();
    k_gemm<<<gemmGrid, 256, GEMM_SMEM>>>(W0, b0);
    k_agg<<<aggGrid, 256>>>();
    k_gemm<<<gemmGrid, 256, GEMM_SMEM>>>(W1, b1);
    k_agg<<<aggGrid, 256>>>();
    k_gemm<<<gemmGrid, 256, GEMM_SMEM>>>(W2, b2);

    k_z<<<aggGrid, 256>>>();
    k_zagg<<<(NN + 255) / 256, 256>>>(out);
}

// round 4
// speedup vs baseline: 1.5558x; 1.3075x over previous
#include <cuda_runtime.h>
#include <cstdint>

// ---------------------------------------------------------------------------
// GCN, 4 layers + heads. R4:
//  - layers 0-2: agg (gather CSR) -> tensor-core GEMM (mma.sync tf32, f32 accum)
//  - layer 3 + PI/V heads collapsed algebraically (layer 3 is linear)
// ---------------------------------------------------------------------------

constexpr int NN = 50000;
constexpr int NE = 800000;
constexpr int F  = 128;

__device__ int    g_outdeg[NN];
__device__ int    g_indeg[NN];
__device__ float  g_nsrc[NN];
__device__ float  g_ndst[NN];
__device__ int    g_rowptr[NN + 1];
__device__ int    g_cursor[NN];
__device__ int    g_esrc[NE];
__device__ float  g_hs[(size_t)NN * F];    // scaled features (gather source)
__device__ float  g_agg[(size_t)NN * F];   // aggregated * norm_dst (GEMM input)
__device__ float2 g_zz[NN];                // (z, z2) per node
__device__ float  g_q[F];                  // W3 @ Wp
__device__ float  g_q2[F];                 // W3 @ Wv
__device__ float  g_cPI;

__device__ __forceinline__ uint32_t f2tf32(float x) {
    uint32_t r; asm("cvt.rna.tf32.f32 %0, %1;" : "=r"(r) : "f"(x)); return r;
}

__device__ __forceinline__ void mma_tf32(float* c, const uint32_t* a,
                                         uint32_t b0, uint32_t b1) {
    asm("mma.sync.aligned.m16n8k8.row.col.f32.tf32.tf32.f32 "
        "{%0,%1,%2,%3},{%4,%5,%6,%7},{%8,%9},{%0,%1,%2,%3};"
        : "+f"(c[0]), "+f"(c[1]), "+f"(c[2]), "+f"(c[3])
        : "r"(a[0]), "r"(a[1]), "r"(a[2]), "r"(a[3]), "r"(b0), "r"(b1));
}

// --------------------------- setup ----------------------------------------

__global__ void k_zero() {
    int i = blockIdx.x * blockDim.x + threadIdx.x;
    if (i < NN) { g_outdeg[i] = 0; g_indeg[i] = 0; }
}

__global__ void k_hist(const int* __restrict__ src, const int* __restrict__ dst) {
    int e = blockIdx.x * blockDim.x + threadIdx.x;
    if (e < NE) {
        atomicAdd(&g_outdeg[src[e]], 1);
        atomicAdd(&g_indeg[dst[e]], 1);
    }
}

// Single-block scan: per-thread chunk of 49 + one 1024-wide block scan.
__global__ void k_scan() {
    constexpr int CH = (NN + 1023) / 1024;   // 49
    __shared__ int ts[1024];
    int t = threadIdx.x;
    int base = t * CH;
    int s = 0;
    for (int i = 0; i < CH; i++) {
        int idx = base + i;
        int v = (idx < NN) ? g_indeg[idx] : 0;
        if (idx < NN) g_rowptr[idx] = s;
        s += v;
    }
    ts[t] = s;
    __syncthreads();
    for (int off = 1; off < 1024; off <<= 1) {
        int v = (t >= off) ? ts[t - off] : 0;
        __syncthreads();
        ts[t] += v;
        __syncthreads();
    }
    int offset = ts[t] - s;
    for (int i = 0; i < CH; i++) {
        int idx = base + i;
        if (idx < NN) {
            int p = g_rowptr[idx] + offset;
            g_rowptr[idx] = p;
            g_cursor[idx] = p;
        }
    }
    if (t == 1023) g_rowptr[NN] = ts[1023];
}

__global__ void k_norm() {
    int i = blockIdx.x * blockDim.x + threadIdx.x;
    if (i < NN) {
        g_nsrc[i] = rsqrtf((float)max(g_outdeg[i], 1));
        g_ndst[i] = rsqrtf((float)max(g_indeg[i], 1));
    }
}

__global__ void k_fill(const int* __restrict__ src, const int* __restrict__ dst) {
    int e = blockIdx.x * blockDim.x + threadIdx.x;
    if (e < NE) {
        int p = atomicAdd(&g_cursor[dst[e]], 1);
        g_esrc[p] = src[e];
    }
}

__global__ void k_scale0(const float* __restrict__ feats) {
    int i = blockIdx.x * blockDim.x + threadIdx.x;
    constexpr int TOT = NN * F / 4;
    if (i < TOT) {
        int node = i >> 5;
        float s = g_nsrc[node];
        float4 x = ((const float4*)feats)[i];
        x.x *= s; x.y *= s; x.z *= s; x.w *= s;
        ((float4*)g_hs)[i] = x;
    }
}

__global__ void k_prep(const float* __restrict__ W3, const float* __restrict__ b3,
                       const float* __restrict__ Wp, const float* __restrict__ bp,
                       const float* __restrict__ Wv, const float* __restrict__ bv,
                       float* __restrict__ out) {
    int k = threadIdx.x;   // 128 threads
    float a = 0.f, c = 0.f;
    for (int j = 0; j < 64; j++) {
        float w = W3[k * 64 + j];
        a += w * Wp[j];
        c += w * Wv[j];
    }
    g_q[k] = a;
    g_q2[k] = c;
    if (k == 0) {
        float cp = 0.f, cv = 0.f;
        for (int j = 0; j < 64; j++) { cp += b3[j] * Wp[j]; cv += b3[j] * Wv[j]; }
        g_cPI = cp + bp[0];
        out[NN] = (float)NN * cv + bv[0];
    }
}

// --------------------------- aggregation ----------------------------------

__global__ void k_agg() {
    int v = blockIdx.x * (blockDim.x >> 5) + (threadIdx.x >> 5);
    if (v >= NN) return;
    int lane = threadIdx.x & 31;
    int beg = g_rowptr[v], end = g_rowptr[v + 1];
    const float4* hs4 = (const float4*)g_hs;
    float4 a0 = make_float4(0.f, 0.f, 0.f, 0.f);
    float4 a1 = a0, a2 = a0, a3 = a0;
    int e = beg;
    for (; e + 3 < end; e += 4) {
        int u0 = g_esrc[e],     u1 = g_esrc[e + 1];
        int u2 = g_esrc[e + 2], u3 = g_esrc[e + 3];
        float4 x0 = hs4[u0 * 32 + lane];
        float4 x1 = hs4[u1 * 32 + lane];
        float4 x2 = hs4[u2 * 32 + lane];
        float4 x3 = hs4[u3 * 32 + lane];
        a0.x += x0.x; a0.y += x0.y; a0.z += x0.z; a0.w += x0.w;
        a1.x += x1.x; a1.y += x1.y; a1.z += x1.z; a1.w += x1.w;
        a2.x += x2.x; a2.y += x2.y; a2.z += x2.z; a2.w += x2.w;
        a3.x += x3.x; a3.y += x3.y; a3.z += x3.z; a3.w += x3.w;
    }
    for (; e < end; e++) {
        int u = g_esrc[e];
        float4 x = hs4[u * 32 + lane];
        a0.x += x.x; a0.y += x.y; a0.z += x.z; a0.w += x.w;
    }
    float nd = g_ndst[v];
    float4 o;
    o.x = ((a0.x + a1.x) + (a2.x + a3.x)) * nd;
    o.y = ((a0.y + a1.y) + (a2.y + a3.y)) * nd;
    o.z = ((a0.z + a1.z) + (a2.z + a3.z)) * nd;
    o.w = ((a0.w + a1.w) + (a2.w + a3.w)) * nd;
    ((float4*)g_agg)[v * 32 + lane] = o;
}

// --------------------------- tensor-core GEMM ------------------------------
// g_hs = relu(g_agg @ W + b) * nsrc; W 128x128 row-major [k][n].
// Block: 128 rows x 128 cols, 256 threads. mma.sync m16n8k8 tf32.
// Warp tile 32x64: 2 m-frags x 8 n-frags. Smem: sA[row][k] stride 132,
// sW[k][n] stride 136 (both chosen for conflict-free fragment LDS).

constexpr int PADA = 132;
constexpr int PADW = 136;
constexpr int GEMM_SMEM = (128 * PADA + 128 * PADW) * 4;   // 137216 B

__global__ void __launch_bounds__(256) k_gemm(const float* __restrict__ W,
                                              const float* __restrict__ b) {
    extern __shared__ uint32_t sm[];
    uint32_t* sA = sm;                 // [row][k] tf32 bits, stride PADA
    uint32_t* sW = sm + 128 * PADA;    // [k][n]  tf32 bits, stride PADW

    int tid  = threadIdx.x;
    int lane = tid & 31;
    int warp = tid >> 5;
    int row0 = blockIdx.x * 128;

    // --- stage A (convert to tf32) ---
    const float4* A4 = (const float4*)g_agg;
    #pragma unroll
    for (int it = 0; it < 16; it++) {
        int i  = it * 256 + tid;          // 0..4095
        int r  = i >> 5;
        int c4 = i & 31;
        int gr = row0 + r;
        float4 v = (gr < NN) ? A4[gr * 32 + c4] : make_float4(0.f, 0.f, 0.f, 0.f);
        uint4 t = make_uint4(f2tf32(v.x), f2tf32(v.y), f2tf32(v.z), f2tf32(v.w));
        *(uint4*)&sA[r * PADA + c4 * 4] = t;
    }
    // --- stage W (convert to tf32) ---
    const float4* W4 = (const float4*)W;
    #pragma unroll
    for (int it = 0; it < 16; it++) {
        int i  = it * 256 + tid;
        int k  = i >> 5;
        int c4 = i & 31;
        float4 v = W4[k * 32 + c4];
        uint4 t = make_uint4(f2tf32(v.x), f2tf32(v.y), f2tf32(v.z), f2tf32(v.w));
        *(uint4*)&sW[k * PADW + c4 * 4] = t;
    }
    __syncthreads();

    int wm = (warp >> 1) * 32;           // warp row offset within tile
    int wn = (warp & 1) * 64;            // warp col offset

    float acc[2][8][4];
    #pragma unroll
    for (int mf = 0; mf < 2; mf++)
        #pragma unroll
        for (int nf = 0; nf < 8; nf++)
            #pragma unroll
            for (int j = 0; j < 4; j++) acc[mf][nf][j] = 0.f;

    int qr = lane >> 2;                  // 0..7
    int qc = lane & 3;                   // 0..3

    #pragma unroll
    for (int ks = 0; ks < 16; ks++) {
        int kb = ks * 8;
        uint32_t a[2][4];
        #pragma unroll
        for (int mf = 0; mf < 2; mf++) {
            int r = wm + mf * 16 + qr;
            a[mf][0] = sA[r * PADA + kb + qc];
            a[mf][1] = sA[(r + 8) * PADA + kb + qc];
            a[mf][2] = sA[r * PADA + kb + qc + 4];
            a[mf][3] = sA[(r + 8) * PADA + kb + qc + 4];
        }
        #pragma unroll
        for (int nf = 0; nf < 8; nf++) {
            int n = wn + nf * 8 + qr;
            uint32_t b0 = sW[(kb + qc) * PADW + n];
            uint32_t b1 = sW[(kb + qc + 4) * PADW + n];
            mma_tf32(acc[0][nf], a[0], b0, b1);
            mma_tf32(acc[1][nf], a[1], b0, b1);
        }
    }

    // --- epilogue: bias + relu + nsrc scale ---
    #pragma unroll
    for (int mf = 0; mf < 2; mf++) {
        int r0 = row0 + wm + mf * 16 + qr;
        int r1 = r0 + 8;
        float s0 = (r0 < NN) ? g_nsrc[r0] : 0.f;
        float s1 = (r1 < NN) ? g_nsrc[r1] : 0.f;
        #pragma unroll
        for (int nf = 0; nf < 8; nf++) {
            int c = wn + nf * 8 + qc * 2;
            float2 bb = *(const float2*)&b[c];
            if (r0 < NN) {
                float2 o;
                o.x = fmaxf(acc[mf][nf][0] + bb.x, 0.f) * s0;
                o.y = fmaxf(acc[mf][nf][1] + bb.y, 0.f) * s0;
                *(float2*)&g_hs[(size_t)r0 * 128 + c] = o;
            }
            if (r1 < NN) {
                float2 o;
                o.x = fmaxf(acc[mf][nf][2] + bb.x, 0.f) * s1;
                o.y = fmaxf(acc[mf][nf][3] + bb.y, 0.f) * s1;
                *(float2*)&g_hs[(size_t)r1 * 128 + c] = o;
            }
        }
    }
}

// ---------------------- collapsed layer 3 + heads --------------------------

__global__ void k_z() {
    int v = blockIdx.x * (blockDim.x >> 5) + (threadIdx.x >> 5);
    if (v >= NN) return;
    int lane = threadIdx.x & 31;
    float4 h = ((const float4*)g_hs)[v * 32 + lane];
    float4 q = ((const float4*)g_q)[lane];
    float4 q2 = ((const float4*)g_q2)[lane];
    float z  = h.x * q.x  + h.y * q.y  + h.z * q.z  + h.w * q.w;
    float z2 = h.x * q2.x + h.y * q2.y + h.z * q2.z + h.w * q2.w;
    #pragma unroll
    for (int off = 16; off; off >>= 1) {
        z  += __shfl_xor_sync(0xffffffff, z,  off);
        z2 += __shfl_xor_sync(0xffffffff, z2, off);
    }
    if (lane == 0) g_zz[v] = make_float2(z, z2);
}

__global__ void k_zagg(float* __restrict__ out) {
    __shared__ float red[256];
    int v = blockIdx.x * blockDim.x + threadIdx.x;
    float vp = 0.f;
    if (v < NN) {
        int beg = g_rowptr[v], end = g_rowptr[v + 1];
        float s0 = 0.f, s1 = 0.f, t0 = 0.f, t1 = 0.f;
        int e = beg;
        for (; e + 1 < end; e += 2) {
            float2 a = g_zz[g_esrc[e]];
            float2 b = g_zz[g_esrc[e + 1]];
            s0 += a.x; t0 += a.y;
            s1 += b.x; t1 += b.y;
        }
        if (e < end) {
            float2 a = g_zz[g_esrc[e]];
            s0 += a.x; t0 += a.y;
        }
        float nd = g_ndst[v];
        out[v] = nd * (s0 + s1) + g_cPI;
        vp = nd * (t0 + t1);
    }
    red[threadIdx.x] = vp;
    __syncthreads();
    for (int off = 128; off; off >>= 1) {
        if (threadIdx.x < off) red[threadIdx.x] += red[threadIdx.x + off];
        __syncthreads();
    }
    if (threadIdx.x == 0) atomicAdd(&out[NN], red[0]);
}

// --------------------------- launch ----------------------------------------

extern "C" void kernel_launch(void* const* d_in, const int* in_sizes, int n_in,
                              void* d_out, int out_size) {
    const float* feats = (const float*)d_in[0];
    const int*   src   = (const int*)d_in[1];
    const int*   dst   = (const int*)d_in[2];
    const float* W0 = (const float*)d_in[3];  const float* b0 = (const float*)d_in[4];
    const float* W1 = (const float*)d_in[5];  const float* b1 = (const float*)d_in[6];
    const float* W2 = (const float*)d_in[7];  const float* b2 = (const float*)d_in[8];
    const float* W3 = (const float*)d_in[9];  const float* b3 = (const float*)d_in[10];
    const float* Wp = (const float*)d_in[11]; const float* bp = (const float*)d_in[12];
    const float* Wv = (const float*)d_in[13]; const float* bv = (const float*)d_in[14];
    float* out = (float*)d_out;

    cudaFuncSetAttribute(k_gemm, cudaFuncAttributeMaxDynamicSharedMemorySize,
                         GEMM_SMEM);

    k_zero<<<(NN + 255) / 256, 256>>>();
    k_hist<<<(NE + 255) / 256, 256>>>(src, dst);
    k_scan<<<1, 1024>>>();
    k_norm<<<(NN + 255) / 256, 256>>>();
    k_fill<<<(NE + 255) / 256, 256>>>(src, dst);
    k_prep<<<1, 128>>>(W3, b3, Wp, bp, Wv, bv, out);
    k_scale0<<<(NN * F / 4 + 255) / 256, 256>>>(feats);

    const int aggGrid  = (NN + 7) / 8;        // 8 warps/block
    const int gemmGrid = (NN + 127) / 128;    // 391

    k_agg<<<aggGrid, 256>>>();
    k_gemm<<<gemmGrid, 256, GEMM_SMEM>>>(W0, b0);
    k_agg<<<aggGrid, 256>>>();
    k_gemm<<<gemmGrid, 256, GEMM_SMEM>>>(W1, b1);
    k_agg<<<aggGrid, 256>>>();
    k_gemm<<<gemmGrid, 256, GEMM_SMEM>>>(W2, b2);

    k_z<<<aggGrid, 256>>>();
    k_zagg<<<(NN + 255) / 256, 256>>>(out);
}